// round 2
// baseline (speedup 1.0000x reference)
#include <cuda_runtime.h>
#include <cuda_bf16.h>

#define N_NODES 50000
#define N_EDGES 800000
#define DIN 128
#define DH  256
#define DOUT 64

// ---------------- scratch (static device memory; no allocations) ------------
__device__ __align__(16) float g_agg1[N_NODES * DIN];   // sum of x[src] per dst
__device__ __align__(16) float g_deg [N_NODES];         // in-degree
__device__ __align__(16) float g_inv [N_NODES];         // 1 / max(deg,1)
__device__ __align__(16) float g_h   [N_NODES * DH];    // relu(layer1)
__device__ __align__(16) float g_P   [N_NODES * 2*DOUT];// 0..63 = h@W2l^T, 64..127 = h@W2r^T
__device__ __align__(16) float g_agg2[N_NODES * DOUT];  // sum of p[src] per dst
__device__ int g_is64;                                   // edge_index dtype flag

// ---------------- edge dtype detect ------------------------------------------
// int64 little-endian with values < 2^31 => every odd 32-bit word is 0.
__global__ void detect_kernel(const unsigned int* __restrict__ ei_words) {
    if (threadIdx.x != 0 || blockIdx.x != 0) return;
    int is64 = 1;
    for (int k = 0; k < 128; ++k) {
        if (ei_words[2 * k + 1] != 0u) { is64 = 0; break; }
    }
    g_is64 = is64;
}

__device__ __forceinline__ long long edge_val(const void* ei, long long idx) {
    if (g_is64) return ((const long long*)ei)[idx];
    return (long long)((const int*)ei)[idx];
}

// ---------------- zero scratch ----------------------------------------------
__global__ void zero_kernel() {
    const int n1 = N_NODES * DIN / 4;
    const int n2 = N_NODES * DOUT / 4;
    const int n3 = N_NODES / 4;
    int idx = blockIdx.x * blockDim.x + threadIdx.x;
    float4 z = make_float4(0.f, 0.f, 0.f, 0.f);
    if (idx < n1) {
        ((float4*)g_agg1)[idx] = z;
    } else if (idx < n1 + n2) {
        ((float4*)g_agg2)[idx - n1] = z;
    } else if (idx < n1 + n2 + n3) {
        ((float4*)g_deg)[idx - n1 - n2] = z;
    }
}

// ---------------- layer-1 edge scatter: agg1[dst] += x[src]; deg[dst]++ -----
__global__ void edge_agg1_kernel(const float* __restrict__ x,
                                 const void* __restrict__ ei) {
    int w    = (blockIdx.x * blockDim.x + threadIdx.x) >> 5;   // one warp / edge
    int lane = threadIdx.x & 31;
    if (w >= N_EDGES) return;
    long long s = edge_val(ei, w);
    long long d = edge_val(ei, N_EDGES + w);
    if ((unsigned long long)s >= N_NODES || (unsigned long long)d >= N_NODES) return;
    float4 v = *(const float4*)(x + s * DIN + lane * 4);
    atomicAdd((float4*)(g_agg1 + d * DIN + lane * 4), v);
    if (lane == 0) atomicAdd(&g_deg[d], 1.0f);
}

// ---------------- invdeg -----------------------------------------------------
__global__ void invdeg_kernel() {
    int i = blockIdx.x * blockDim.x + threadIdx.x;
    if (i < N_NODES) g_inv[i] = 1.0f / fmaxf(g_deg[i], 1.0f);
}

// ---------------- GEMM tiles -------------------------------------------------
#define BM 128
#define BN 128
#define BK 16
#define LDS_PAD 4

// Layer 1: h = relu( (agg1*inv) @ W1l^T + x @ W1r^T + b1 )  [M=50000, N=256, K=128]
__global__ void __launch_bounds__(256)
gemm1_kernel(const float* __restrict__ x,
             const float* __restrict__ W1l, const float* __restrict__ W1r,
             const float* __restrict__ b1) {
    __shared__ float As[BK][BM + LDS_PAD];
    __shared__ float Bs[BK][BN + LDS_PAD];

    const int tid = threadIdx.x;
    const int tx = tid & 15;
    const int ty = tid >> 4;
    const int m0 = blockIdx.x * BM;
    const int n0 = blockIdx.y * BN;

    float acc[8][8];
#pragma unroll
    for (int i = 0; i < 8; ++i)
#pragma unroll
        for (int j = 0; j < 8; ++j) acc[i][j] = 0.f;

    const int lrow = tid >> 2;
    const int ks   = (tid & 3) * 4;

    for (int pass = 0; pass < 2; ++pass) {
        const float* A = pass ? x : g_agg1;
        const float* W = pass ? W1r : W1l;
        const bool scale = (pass == 0);

        for (int k0 = 0; k0 < DIN; k0 += BK) {
#pragma unroll
            for (int r = 0; r < 2; ++r) {
                int row = lrow + r * 64;
                int grow = m0 + row;
                float4 v = make_float4(0.f, 0.f, 0.f, 0.f);
                if (grow < N_NODES) {
                    v = *(const float4*)&A[(long long)grow * DIN + k0 + ks];
                    if (scale) {
                        float s = g_inv[grow];
                        v.x *= s; v.y *= s; v.z *= s; v.w *= s;
                    }
                }
                As[ks + 0][row] = v.x; As[ks + 1][row] = v.y;
                As[ks + 2][row] = v.z; As[ks + 3][row] = v.w;
            }
#pragma unroll
            for (int r = 0; r < 2; ++r) {
                int row = lrow + r * 64;
                int n = n0 + row;
                float4 v = *(const float4*)&W[(long long)n * DIN + k0 + ks];
                Bs[ks + 0][row] = v.x; Bs[ks + 1][row] = v.y;
                Bs[ks + 2][row] = v.z; Bs[ks + 3][row] = v.w;
            }
            __syncthreads();
#pragma unroll
            for (int k = 0; k < BK; ++k) {
                float4 a0 = *(const float4*)&As[k][ty * 8];
                float4 a1 = *(const float4*)&As[k][ty * 8 + 4];
                float4 b0 = *(const float4*)&Bs[k][tx * 8];
                float4 b1v = *(const float4*)&Bs[k][tx * 8 + 4];
                float a[8] = {a0.x, a0.y, a0.z, a0.w, a1.x, a1.y, a1.z, a1.w};
                float b[8] = {b0.x, b0.y, b0.z, b0.w, b1v.x, b1v.y, b1v.z, b1v.w};
#pragma unroll
                for (int i = 0; i < 8; ++i)
#pragma unroll
                    for (int j = 0; j < 8; ++j) acc[i][j] += a[i] * b[j];
            }
            __syncthreads();
        }
    }
#pragma unroll
    for (int i = 0; i < 8; ++i) {
        int row = m0 + ty * 8 + i;
        if (row >= N_NODES) continue;
#pragma unroll
        for (int j = 0; j < 8; ++j) {
            int col = n0 + tx * 8 + j;
            float v = acc[i][j] + b1[col];
            g_h[(long long)row * DH + col] = fmaxf(v, 0.f);
        }
    }
}

// Layer 2 projections: P[:,0:64] = h @ W2l^T ; P[:,64:128] = h @ W2r^T
__global__ void __launch_bounds__(256)
gemm2_kernel(const float* __restrict__ W2l, const float* __restrict__ W2r) {
    __shared__ float As[BK][BM + LDS_PAD];
    __shared__ float Bs[BK][BN + LDS_PAD];

    const int tid = threadIdx.x;
    const int tx = tid & 15;
    const int ty = tid >> 4;
    const int m0 = blockIdx.x * BM;

    float acc[8][8];
#pragma unroll
    for (int i = 0; i < 8; ++i)
#pragma unroll
        for (int j = 0; j < 8; ++j) acc[i][j] = 0.f;

    const int lrow = tid >> 2;
    const int ks   = (tid & 3) * 4;

    for (int k0 = 0; k0 < DH; k0 += BK) {
#pragma unroll
        for (int r = 0; r < 2; ++r) {
            int row = lrow + r * 64;
            int grow = m0 + row;
            float4 v = make_float4(0.f, 0.f, 0.f, 0.f);
            if (grow < N_NODES)
                v = *(const float4*)&g_h[(long long)grow * DH + k0 + ks];
            As[ks + 0][row] = v.x; As[ks + 1][row] = v.y;
            As[ks + 2][row] = v.z; As[ks + 3][row] = v.w;
        }
#pragma unroll
        for (int r = 0; r < 2; ++r) {
            int row = lrow + r * 64;
            const float* Wrow = (row < DOUT) ? (W2l + (long long)row * DH)
                                             : (W2r + (long long)(row - DOUT) * DH);
            float4 v = *(const float4*)&Wrow[k0 + ks];
            Bs[ks + 0][row] = v.x; Bs[ks + 1][row] = v.y;
            Bs[ks + 2][row] = v.z; Bs[ks + 3][row] = v.w;
        }
        __syncthreads();
#pragma unroll
        for (int k = 0; k < BK; ++k) {
            float4 a0 = *(const float4*)&As[k][ty * 8];
            float4 a1 = *(const float4*)&As[k][ty * 8 + 4];
            float4 b0 = *(const float4*)&Bs[k][tx * 8];
            float4 b1v = *(const float4*)&Bs[k][tx * 8 + 4];
            float a[8] = {a0.x, a0.y, a0.z, a0.w, a1.x, a1.y, a1.z, a1.w};
            float b[8] = {b0.x, b0.y, b0.z, b0.w, b1v.x, b1v.y, b1v.z, b1v.w};
#pragma unroll
            for (int i = 0; i < 8; ++i)
#pragma unroll
                for (int j = 0; j < 8; ++j) acc[i][j] += a[i] * b[j];
        }
        __syncthreads();
    }
#pragma unroll
    for (int i = 0; i < 8; ++i) {
        int row = m0 + ty * 8 + i;
        if (row >= N_NODES) continue;
#pragma unroll
        for (int j = 0; j < 8; ++j) {
            int col = tx * 8 + j;
            g_P[(long long)row * 2 * DOUT + col] = acc[i][j];
        }
    }
}

// ---------------- layer-2 edge scatter on projected p (64 dims) -------------
__global__ void edge_agg2_kernel(const void* __restrict__ ei) {
    int t   = blockIdx.x * blockDim.x + threadIdx.x;
    int e   = t >> 4;
    int sub = t & 15;
    if (e >= N_EDGES) return;
    long long s = edge_val(ei, e);
    long long d = edge_val(ei, N_EDGES + e);
    if ((unsigned long long)s >= N_NODES || (unsigned long long)d >= N_NODES) return;
    float4 v = *(const float4*)(g_P + s * (2 * DOUT) + sub * 4);
    atomicAdd((float4*)(g_agg2 + d * DOUT + sub * 4), v);
}

// ---------------- final combine ----------------------------------------------
__global__ void final_kernel(const float* __restrict__ b2, float* __restrict__ out) {
    int idx = blockIdx.x * blockDim.x + threadIdx.x;
    if (idx >= N_NODES * DOUT) return;
    int i = idx >> 6;
    int n = idx & 63;
    out[idx] = g_agg2[idx] * g_inv[i] + g_P[(long long)i * 2 * DOUT + DOUT + n] + b2[n];
}

// ---------------- launch ------------------------------------------------------
extern "C" void kernel_launch(void* const* d_in, const int* in_sizes, int n_in,
                              void* d_out, int out_size) {
    const float* x   = (const float*)d_in[0];
    const void*  ei  = d_in[1];
    const float* W1l = (const float*)d_in[2];
    const float* W1r = (const float*)d_in[3];
    const float* b1  = (const float*)d_in[4];
    const float* W2l = (const float*)d_in[5];
    const float* W2r = (const float*)d_in[6];
    const float* b2  = (const float*)d_in[7];
    float*       out = (float*)d_out;

    detect_kernel<<<1, 32>>>((const unsigned int*)ei);
    {
        int total4 = N_NODES * DIN / 4 + N_NODES * DOUT / 4 + N_NODES / 4;
        zero_kernel<<<(total4 + 255) / 256, 256>>>();
    }
    edge_agg1_kernel<<<(N_EDGES * 32 + 255) / 256, 256>>>(x, ei);
    invdeg_kernel<<<(N_NODES + 255) / 256, 256>>>();
    {
        dim3 grid((N_NODES + BM - 1) / BM, DH / BN);
        gemm1_kernel<<<grid, 256>>>(x, W1l, W1r, b1);
    }
    {
        dim3 grid((N_NODES + BM - 1) / BM, 1);
        gemm2_kernel<<<grid, 256>>>(W2l, W2r);
    }
    edge_agg2_kernel<<<(N_EDGES * 16 + 255) / 256, 256>>>(ei);
    final_kernel<<<(N_NODES * DOUT + 255) / 256, 256>>>(b2, out);
}

// round 3
// speedup vs baseline: 1.1509x; 1.1509x over previous
#include <cuda_runtime.h>
#include <cuda_bf16.h>

#define N_NODES 50000
#define N_EDGES 800000
#define DIN 128
#define DH  256
#define DOUT 64

// ---------------- scratch (static device memory; no allocations) ------------
__device__ __align__(16) float g_agg1[N_NODES * DIN];    // mean of x[src] per dst
__device__ __align__(16) float g_inv [N_NODES];          // 1 / max(deg,1)
__device__ __align__(16) float g_h   [N_NODES * DH];     // relu(layer1)
__device__ __align__(16) float g_P   [N_NODES * 2*DOUT]; // 0..63 = h@W2l^T, 64..127 = h@W2r^T
__device__ int g_rowptr[N_NODES + 1];
__device__ int g_cnt   [N_NODES];        // counts, then reused as fill cursor
__device__ int g_col   [N_EDGES];        // CSR column (src) indices grouped by dst
__device__ int g_is64;

// ---------------- edge dtype detect ------------------------------------------
__global__ void detect_kernel(const unsigned int* __restrict__ ei_words) {
    if (threadIdx.x != 0 || blockIdx.x != 0) return;
    int is64 = 1;
    for (int k = 0; k < 128; ++k)
        if (ei_words[2 * k + 1] != 0u) { is64 = 0; break; }
    g_is64 = is64;
}

__device__ __forceinline__ long long edge_val(const void* ei, long long idx) {
    if (g_is64) return ((const long long*)ei)[idx];
    return (long long)((const int*)ei)[idx];
}

// ---------------- CSR build ----------------------------------------------------
__global__ void zero_cnt_kernel() {
    int i = blockIdx.x * blockDim.x + threadIdx.x;
    if (i < N_NODES) g_cnt[i] = 0;
}

__global__ void count_kernel(const void* __restrict__ ei) {
    int e = blockIdx.x * blockDim.x + threadIdx.x;
    if (e >= N_EDGES) return;
    long long d = edge_val(ei, N_EDGES + e);
    if ((unsigned long long)d < N_NODES) atomicAdd(&g_cnt[(int)d], 1);
}

// single-block exclusive scan over 50000 counts
__global__ void scan_kernel() {
    __shared__ int ssum[1024];
    const int t = threadIdx.x;
    const int CH = (N_NODES + 1023) / 1024;      // 49
    int base = t * CH;
    int len = N_NODES - base; if (len < 0) len = 0; if (len > CH) len = CH;
    int s = 0;
    for (int i = 0; i < len; ++i) s += g_cnt[base + i];
    ssum[t] = s;
    __syncthreads();
    for (int off = 1; off < 1024; off <<= 1) {
        int v = (t >= off) ? ssum[t - off] : 0;
        __syncthreads();
        ssum[t] += v;
        __syncthreads();
    }
    int run = ssum[t] - s;                       // exclusive offset
    for (int i = 0; i < len; ++i) {
        g_rowptr[base + i] = run;
        run += g_cnt[base + i];
    }
    if (t == 1023) g_rowptr[N_NODES] = ssum[1023];
}

__global__ void cursor_init_kernel() {
    int i = blockIdx.x * blockDim.x + threadIdx.x;
    if (i >= N_NODES) return;
    int r0 = g_rowptr[i], r1 = g_rowptr[i + 1];
    g_cnt[i] = r0;                               // reuse as cursor
    int deg = r1 - r0;
    g_inv[i] = 1.0f / (float)(deg > 0 ? deg : 1);
}

__global__ void fill_kernel(const void* __restrict__ ei) {
    int e = blockIdx.x * blockDim.x + threadIdx.x;
    if (e >= N_EDGES) return;
    long long s = edge_val(ei, e);
    long long d = edge_val(ei, N_EDGES + e);
    if ((unsigned long long)s >= N_NODES || (unsigned long long)d >= N_NODES) return;
    int pos = atomicAdd(&g_cnt[(int)d], 1);
    g_col[pos] = (int)s;
}

// ---------------- layer-1 aggregation (gather, warp per node) ----------------
__global__ void __launch_bounds__(256)
agg1_kernel(const float* __restrict__ x) {
    int w    = (blockIdx.x * blockDim.x + threadIdx.x) >> 5;
    int lane = threadIdx.x & 31;
    if (w >= N_NODES) return;
    int start = g_rowptr[w], end = g_rowptr[w + 1];
    const float4* xv = (const float4*)x;         // row stride 32 float4
    float4 acc = make_float4(0.f, 0.f, 0.f, 0.f);
    int p = start;
    for (; p + 4 <= end; p += 4) {
        int s0 = g_col[p], s1 = g_col[p + 1], s2 = g_col[p + 2], s3 = g_col[p + 3];
        float4 v0 = xv[(long long)s0 * 32 + lane];
        float4 v1 = xv[(long long)s1 * 32 + lane];
        float4 v2 = xv[(long long)s2 * 32 + lane];
        float4 v3 = xv[(long long)s3 * 32 + lane];
        acc.x += v0.x + v1.x + v2.x + v3.x;
        acc.y += v0.y + v1.y + v2.y + v3.y;
        acc.z += v0.z + v1.z + v2.z + v3.z;
        acc.w += v0.w + v1.w + v2.w + v3.w;
    }
    for (; p < end; ++p) {
        float4 v = xv[(long long)g_col[p] * 32 + lane];
        acc.x += v.x; acc.y += v.y; acc.z += v.z; acc.w += v.w;
    }
    float inv = g_inv[w];
    acc.x *= inv; acc.y *= inv; acc.z *= inv; acc.w *= inv;
    ((float4*)g_agg1)[(long long)w * 32 + lane] = acc;
}

// ---------------- GEMM tiles -------------------------------------------------
#define BM 128
#define BN 128
#define BK 16
#define LDS_PAD 4

// Layer 1: h = relu( agg1 @ W1l^T + x @ W1r^T + b1 )  [M=50000, N=256, K=128]
__global__ void __launch_bounds__(256)
gemm1_kernel(const float* __restrict__ x,
             const float* __restrict__ W1l, const float* __restrict__ W1r,
             const float* __restrict__ b1) {
    __shared__ float As[BK][BM + LDS_PAD];
    __shared__ float Bs[BK][BN + LDS_PAD];

    const int tid = threadIdx.x;
    const int tx = tid & 15;
    const int ty = tid >> 4;
    const int m0 = blockIdx.x * BM;
    const int n0 = blockIdx.y * BN;

    float acc[8][8];
#pragma unroll
    for (int i = 0; i < 8; ++i)
#pragma unroll
        for (int j = 0; j < 8; ++j) acc[i][j] = 0.f;

    const int lrow = tid >> 2;
    const int ks   = (tid & 3) * 4;

    for (int pass = 0; pass < 2; ++pass) {
        const float* A = pass ? x : g_agg1;
        const float* W = pass ? W1r : W1l;

        for (int k0 = 0; k0 < DIN; k0 += BK) {
#pragma unroll
            for (int r = 0; r < 2; ++r) {
                int row = lrow + r * 64;
                int grow = m0 + row;
                float4 v = make_float4(0.f, 0.f, 0.f, 0.f);
                if (grow < N_NODES)
                    v = *(const float4*)&A[(long long)grow * DIN + k0 + ks];
                As[ks + 0][row] = v.x; As[ks + 1][row] = v.y;
                As[ks + 2][row] = v.z; As[ks + 3][row] = v.w;
            }
#pragma unroll
            for (int r = 0; r < 2; ++r) {
                int row = lrow + r * 64;
                int n = n0 + row;
                float4 v = *(const float4*)&W[(long long)n * DIN + k0 + ks];
                Bs[ks + 0][row] = v.x; Bs[ks + 1][row] = v.y;
                Bs[ks + 2][row] = v.z; Bs[ks + 3][row] = v.w;
            }
            __syncthreads();
#pragma unroll
            for (int k = 0; k < BK; ++k) {
                float4 a0 = *(const float4*)&As[k][ty * 8];
                float4 a1 = *(const float4*)&As[k][ty * 8 + 4];
                float4 b0 = *(const float4*)&Bs[k][tx * 8];
                float4 b1v = *(const float4*)&Bs[k][tx * 8 + 4];
                float a[8] = {a0.x, a0.y, a0.z, a0.w, a1.x, a1.y, a1.z, a1.w};
                float b[8] = {b0.x, b0.y, b0.z, b0.w, b1v.x, b1v.y, b1v.z, b1v.w};
#pragma unroll
                for (int i = 0; i < 8; ++i)
#pragma unroll
                    for (int j = 0; j < 8; ++j) acc[i][j] += a[i] * b[j];
            }
            __syncthreads();
        }
    }
#pragma unroll
    for (int i = 0; i < 8; ++i) {
        int row = m0 + ty * 8 + i;
        if (row >= N_NODES) continue;
#pragma unroll
        for (int j = 0; j < 8; ++j) {
            int col = n0 + tx * 8 + j;
            float v = acc[i][j] + b1[col];
            g_h[(long long)row * DH + col] = fmaxf(v, 0.f);
        }
    }
}

// Layer 2 projections: P[:,0:64] = h @ W2l^T ; P[:,64:128] = h @ W2r^T
__global__ void __launch_bounds__(256)
gemm2_kernel(const float* __restrict__ W2l, const float* __restrict__ W2r) {
    __shared__ float As[BK][BM + LDS_PAD];
    __shared__ float Bs[BK][BN + LDS_PAD];

    const int tid = threadIdx.x;
    const int tx = tid & 15;
    const int ty = tid >> 4;
    const int m0 = blockIdx.x * BM;

    float acc[8][8];
#pragma unroll
    for (int i = 0; i < 8; ++i)
#pragma unroll
        for (int j = 0; j < 8; ++j) acc[i][j] = 0.f;

    const int lrow = tid >> 2;
    const int ks   = (tid & 3) * 4;

    for (int k0 = 0; k0 < DH; k0 += BK) {
#pragma unroll
        for (int r = 0; r < 2; ++r) {
            int row = lrow + r * 64;
            int grow = m0 + row;
            float4 v = make_float4(0.f, 0.f, 0.f, 0.f);
            if (grow < N_NODES)
                v = *(const float4*)&g_h[(long long)grow * DH + k0 + ks];
            As[ks + 0][row] = v.x; As[ks + 1][row] = v.y;
            As[ks + 2][row] = v.z; As[ks + 3][row] = v.w;
        }
#pragma unroll
        for (int r = 0; r < 2; ++r) {
            int row = lrow + r * 64;
            const float* Wrow = (row < DOUT) ? (W2l + (long long)row * DH)
                                             : (W2r + (long long)(row - DOUT) * DH);
            float4 v = *(const float4*)&Wrow[k0 + ks];
            Bs[ks + 0][row] = v.x; Bs[ks + 1][row] = v.y;
            Bs[ks + 2][row] = v.z; Bs[ks + 3][row] = v.w;
        }
        __syncthreads();
#pragma unroll
        for (int k = 0; k < BK; ++k) {
            float4 a0 = *(const float4*)&As[k][ty * 8];
            float4 a1 = *(const float4*)&As[k][ty * 8 + 4];
            float4 b0 = *(const float4*)&Bs[k][tx * 8];
            float4 b1v = *(const float4*)&Bs[k][tx * 8 + 4];
            float a[8] = {a0.x, a0.y, a0.z, a0.w, a1.x, a1.y, a1.z, a1.w};
            float b[8] = {b0.x, b0.y, b0.z, b0.w, b1v.x, b1v.y, b1v.z, b1v.w};
#pragma unroll
            for (int i = 0; i < 8; ++i)
#pragma unroll
                for (int j = 0; j < 8; ++j) acc[i][j] += a[i] * b[j];
        }
        __syncthreads();
    }
#pragma unroll
    for (int i = 0; i < 8; ++i) {
        int row = m0 + ty * 8 + i;
        if (row >= N_NODES) continue;
#pragma unroll
        for (int j = 0; j < 8; ++j) {
            int col = tx * 8 + j;
            g_P[(long long)row * 2 * DOUT + col] = acc[i][j];
        }
    }
}

// ---- layer-2 aggregation + combine, fused (gather, warp per node) -----------
__global__ void __launch_bounds__(256)
agg2_final_kernel(const float* __restrict__ b2, float* __restrict__ out) {
    int w    = (blockIdx.x * blockDim.x + threadIdx.x) >> 5;
    int lane = threadIdx.x & 31;
    if (w >= N_NODES) return;
    int start = g_rowptr[w], end = g_rowptr[w + 1];
    const float2* Pv = (const float2*)g_P;       // row stride 64 float2
    float2 acc = make_float2(0.f, 0.f);
    int p = start;
    for (; p + 4 <= end; p += 4) {
        int s0 = g_col[p], s1 = g_col[p + 1], s2 = g_col[p + 2], s3 = g_col[p + 3];
        float2 v0 = Pv[(long long)s0 * 64 + lane];
        float2 v1 = Pv[(long long)s1 * 64 + lane];
        float2 v2 = Pv[(long long)s2 * 64 + lane];
        float2 v3 = Pv[(long long)s3 * 64 + lane];
        acc.x += v0.x + v1.x + v2.x + v3.x;
        acc.y += v0.y + v1.y + v2.y + v3.y;
    }
    for (; p < end; ++p) {
        float2 v = Pv[(long long)g_col[p] * 64 + lane];
        acc.x += v.x; acc.y += v.y;
    }
    float inv = g_inv[w];
    float2 root = Pv[(long long)w * 64 + 32 + lane];   // cols 64..127 = h@W2r^T
    float2 bias = ((const float2*)b2)[lane];
    float2 o;
    o.x = acc.x * inv + root.x + bias.x;
    o.y = acc.y * inv + root.y + bias.y;
    ((float2*)out)[(long long)w * 32 + lane] = o;
}

// ---------------- launch ------------------------------------------------------
extern "C" void kernel_launch(void* const* d_in, const int* in_sizes, int n_in,
                              void* d_out, int out_size) {
    const float* x   = (const float*)d_in[0];
    const void*  ei  = d_in[1];
    const float* W1l = (const float*)d_in[2];
    const float* W1r = (const float*)d_in[3];
    const float* b1  = (const float*)d_in[4];
    const float* W2l = (const float*)d_in[5];
    const float* W2r = (const float*)d_in[6];
    const float* b2  = (const float*)d_in[7];
    float*       out = (float*)d_out;

    detect_kernel<<<1, 32>>>((const unsigned int*)ei);
    zero_cnt_kernel<<<(N_NODES + 255) / 256, 256>>>();
    count_kernel<<<(N_EDGES + 255) / 256, 256>>>(ei);
    scan_kernel<<<1, 1024>>>();
    cursor_init_kernel<<<(N_NODES + 255) / 256, 256>>>();
    fill_kernel<<<(N_EDGES + 255) / 256, 256>>>(ei);

    agg1_kernel<<<(N_NODES * 32 + 255) / 256, 256>>>(x);
    {
        dim3 grid((N_NODES + BM - 1) / BM, DH / BN);
        gemm1_kernel<<<grid, 256>>>(x, W1l, W1r, b1);
    }
    {
        dim3 grid((N_NODES + BM - 1) / BM, 1);
        gemm2_kernel<<<grid, 256>>>(W2l, W2r);
    }
    agg2_final_kernel<<<(N_NODES * 32 + 255) / 256, 256>>>(b2, out);
}

// round 4
// speedup vs baseline: 2.1436x; 1.8624x over previous
#include <cuda_runtime.h>
#include <cuda_bf16.h>
#include <cstdint>

#define N_NODES 50000
#define N_EDGES 800000
#define DIN 128
#define DH  256
#define DOUT 64
#define NB_SCAN 49   // ceil(50000/1024)

// ---------------- scratch ------------------------------------------------------
__device__ __align__(16) float g_agg1[N_NODES * DIN];
__device__ __align__(16) float g_inv [N_NODES];
__device__ __align__(16) float g_h   [N_NODES * DH];
__device__ __align__(16) float g_P   [N_NODES * 2*DOUT];
__device__ int g_rowptr[N_NODES + 1];
__device__ int g_cnt   [N_NODES];
__device__ int g_col   [N_EDGES];
__device__ int g_bsum  [64];
__device__ int g_boff  [64];
__device__ int g_is64;

// ---------------- edge dtype detect -------------------------------------------
__global__ void detect_kernel(const unsigned int* __restrict__ ei_words) {
    if (threadIdx.x != 0 || blockIdx.x != 0) return;
    int is64 = 1;
    for (int k = 0; k < 128; ++k)
        if (ei_words[2 * k + 1] != 0u) { is64 = 0; break; }
    g_is64 = is64;
}
__device__ __forceinline__ long long edge_val(const void* ei, long long idx) {
    if (g_is64) return ((const long long*)ei)[idx];
    return (long long)((const int*)ei)[idx];
}

// ---------------- CSR build ----------------------------------------------------
__global__ void zero_cnt_kernel() {
    int i = blockIdx.x * blockDim.x + threadIdx.x;
    if (i < N_NODES) g_cnt[i] = 0;
}
__global__ void count_kernel(const void* __restrict__ ei) {
    int e = blockIdx.x * blockDim.x + threadIdx.x;
    if (e >= N_EDGES) return;
    long long d = edge_val(ei, N_EDGES + e);
    if ((unsigned long long)d < N_NODES) atomicAdd(&g_cnt[(int)d], 1);
}

// pass 1: per-block sums (1024 elems / block)
__global__ void blocksum_kernel() {
    int b = blockIdx.x, t = threadIdx.x;
    int i0 = b * 1024 + t * 4;
    int s = 0;
#pragma unroll
    for (int k = 0; k < 4; ++k) { int i = i0 + k; if (i < N_NODES) s += g_cnt[i]; }
    for (int off = 16; off > 0; off >>= 1) s += __shfl_down_sync(0xffffffffu, s, off);
    __shared__ int ws[8];
    int lane = t & 31, w = t >> 5;
    if (lane == 0) ws[w] = s;
    __syncthreads();
    if (t == 0) { int tot = 0; for (int k = 0; k < 8; ++k) tot += ws[k]; g_bsum[b] = tot; }
}
// pass 2: exclusive scan of 49 block sums
__global__ void bscan_kernel() {
    __shared__ int sv[64];
    int t = threadIdx.x;
    int v = (t < NB_SCAN) ? g_bsum[t] : 0;
    sv[t] = v;
    __syncthreads();
    for (int off = 1; off < 64; off <<= 1) {
        int u = (t >= off) ? sv[t - off] : 0;
        __syncthreads();
        sv[t] += u;
        __syncthreads();
    }
    g_boff[t] = sv[t] - v;
}
// pass 3: per-block scan + rowptr write
__global__ void rowptr_kernel() {
    __shared__ int warp_tot[8];
    __shared__ int warp_off[8];
    int b = blockIdx.x, t = threadIdx.x;
    int lane = t & 31, w = t >> 5;
    int i0 = b * 1024 + t * 4;
    int c[4];
#pragma unroll
    for (int k = 0; k < 4; ++k) { int i = i0 + k; c[k] = (i < N_NODES) ? g_cnt[i] : 0; }
    int s = c[0] + c[1] + c[2] + c[3];
    int pre = s;
    for (int off = 1; off < 32; off <<= 1) {
        int n = __shfl_up_sync(0xffffffffu, pre, off);
        if (lane >= off) pre += n;
    }
    if (lane == 31) warp_tot[w] = pre;
    __syncthreads();
    if (w == 0) {
        int v = (lane < 8) ? warp_tot[lane] : 0;
        int orig = v;
        for (int off = 1; off < 8; off <<= 1) {
            int n = __shfl_up_sync(0xffffffffu, v, off);
            if (lane >= off) v += n;
        }
        if (lane < 8) warp_off[lane] = v - orig;
    }
    __syncthreads();
    int r = g_boff[b] + warp_off[w] + (pre - s);
#pragma unroll
    for (int k = 0; k < 4; ++k) {
        int i = i0 + k;
        if (i < N_NODES) {
            g_rowptr[i] = r;
            r += c[k];
            if (i == N_NODES - 1) g_rowptr[N_NODES] = r;
        }
    }
}
__global__ void cursor_init_kernel() {
    int i = blockIdx.x * blockDim.x + threadIdx.x;
    if (i >= N_NODES) return;
    int r0 = g_rowptr[i], r1 = g_rowptr[i + 1];
    g_cnt[i] = r0;
    int deg = r1 - r0;
    g_inv[i] = 1.0f / (float)(deg > 0 ? deg : 1);
}
__global__ void fill_kernel(const void* __restrict__ ei) {
    int e = blockIdx.x * blockDim.x + threadIdx.x;
    if (e >= N_EDGES) return;
    long long s = edge_val(ei, e);
    long long d = edge_val(ei, N_EDGES + e);
    if ((unsigned long long)s >= N_NODES || (unsigned long long)d >= N_NODES) return;
    int pos = atomicAdd(&g_cnt[(int)d], 1);
    g_col[pos] = (int)s;
}

// ---------------- layer-1 aggregation (gather, warp per node) ------------------
__global__ void __launch_bounds__(256)
agg1_kernel(const float* __restrict__ x) {
    int w    = (blockIdx.x * blockDim.x + threadIdx.x) >> 5;
    int lane = threadIdx.x & 31;
    if (w >= N_NODES) return;
    int start = g_rowptr[w], end = g_rowptr[w + 1];
    const float4* xv = (const float4*)x;
    float4 acc = make_float4(0.f, 0.f, 0.f, 0.f);
    int p = start;
    for (; p + 4 <= end; p += 4) {
        int s0 = g_col[p], s1 = g_col[p + 1], s2 = g_col[p + 2], s3 = g_col[p + 3];
        float4 v0 = xv[(long long)s0 * 32 + lane];
        float4 v1 = xv[(long long)s1 * 32 + lane];
        float4 v2 = xv[(long long)s2 * 32 + lane];
        float4 v3 = xv[(long long)s3 * 32 + lane];
        acc.x += v0.x + v1.x + v2.x + v3.x;
        acc.y += v0.y + v1.y + v2.y + v3.y;
        acc.z += v0.z + v1.z + v2.z + v3.z;
        acc.w += v0.w + v1.w + v2.w + v3.w;
    }
    for (; p < end; ++p) {
        float4 v = xv[(long long)g_col[p] * 32 + lane];
        acc.x += v.x; acc.y += v.y; acc.z += v.z; acc.w += v.w;
    }
    float inv = g_inv[w];
    acc.x *= inv; acc.y *= inv; acc.z *= inv; acc.w *= inv;
    ((float4*)g_agg1)[(long long)w * 32 + lane] = acc;
}

// ================= bf16x3 tensor-core GEMM machinery ===========================
// block tile 128x128, 8 warps, warp tile 32x64, K-chunk 32 fp32 (2 k16 steps)
#define SM_LD 40   // smem row stride in bf16 (32 + 8 pad -> conflict-free ldmatrix)

__device__ __forceinline__ uint32_t pack_bf16x2(__nv_bfloat16 a, __nv_bfloat16 b) {
    return (uint32_t)__bfloat16_as_ushort(a) | ((uint32_t)__bfloat16_as_ushort(b) << 16);
}
__device__ __forceinline__ void split2(float v, __nv_bfloat16& h, __nv_bfloat16& l) {
    h = __float2bfloat16(v);
    l = __float2bfloat16(v - __bfloat162float(h));
}
__device__ __forceinline__ void lds_x4(uint32_t addr, uint32_t& r0, uint32_t& r1,
                                       uint32_t& r2, uint32_t& r3) {
    asm volatile("ldmatrix.sync.aligned.m8n8.x4.shared.b16 {%0,%1,%2,%3}, [%4];\n"
                 : "=r"(r0), "=r"(r1), "=r"(r2), "=r"(r3) : "r"(addr));
}
__device__ __forceinline__ void mma_bf16(float* c, const uint32_t* a, uint32_t b0, uint32_t b1) {
    asm volatile(
        "mma.sync.aligned.m16n8k16.row.col.f32.bf16.bf16.f32 "
        "{%0,%1,%2,%3}, {%4,%5,%6,%7}, {%8,%9}, {%0,%1,%2,%3};\n"
        : "+f"(c[0]), "+f"(c[1]), "+f"(c[2]), "+f"(c[3])
        : "r"(a[0]), "r"(a[1]), "r"(a[2]), "r"(a[3]), "r"(b0), "r"(b1));
}

// load 128x32 fp32 tile -> hi/lo bf16 smem tiles
__device__ __forceinline__ void load_split_tile(
    const float* __restrict__ G, int row0, int row_limit, int ldk, int k0,
    __nv_bfloat16 (*hi)[SM_LD], __nv_bfloat16 (*lo)[SM_LD], int tid)
{
    int fr = tid >> 3, fc = tid & 7;
#pragma unroll
    for (int s = 0; s < 4; ++s) {
        int row = s * 32 + fr;
        int grow = row0 + row;
        float4 v = make_float4(0.f, 0.f, 0.f, 0.f);
        if (grow < row_limit)
            v = *(const float4*)&G[(size_t)grow * ldk + k0 + fc * 4];
        __nv_bfloat16 h0, l0, h1, l1, h2, l2, h3, l3;
        split2(v.x, h0, l0); split2(v.y, h1, l1);
        split2(v.z, h2, l2); split2(v.w, h3, l3);
        *(uint32_t*)&hi[row][fc * 4]     = pack_bf16x2(h0, h1);
        *(uint32_t*)&hi[row][fc * 4 + 2] = pack_bf16x2(h2, h3);
        *(uint32_t*)&lo[row][fc * 4]     = pack_bf16x2(l0, l1);
        *(uint32_t*)&lo[row][fc * 4 + 2] = pack_bf16x2(l2, l3);
    }
}
// packed W2 loader: rows 0..63 <- W2l, 64..127 <- W2r (ldk = 256)
__device__ __forceinline__ void load_split_tile_w2(
    const float* __restrict__ W2l, const float* __restrict__ W2r, int k0,
    __nv_bfloat16 (*hi)[SM_LD], __nv_bfloat16 (*lo)[SM_LD], int tid)
{
    int fr = tid >> 3, fc = tid & 7;
#pragma unroll
    for (int s = 0; s < 4; ++s) {
        int row = s * 32 + fr;
        const float* src = (row < DOUT) ? &W2l[(size_t)row * DH]
                                        : &W2r[(size_t)(row - DOUT) * DH];
        float4 v = *(const float4*)&src[k0 + fc * 4];
        __nv_bfloat16 h0, l0, h1, l1, h2, l2, h3, l3;
        split2(v.x, h0, l0); split2(v.y, h1, l1);
        split2(v.z, h2, l2); split2(v.w, h3, l3);
        *(uint32_t*)&hi[row][fc * 4]     = pack_bf16x2(h0, h1);
        *(uint32_t*)&hi[row][fc * 4 + 2] = pack_bf16x2(h2, h3);
        *(uint32_t*)&lo[row][fc * 4]     = pack_bf16x2(l0, l1);
        *(uint32_t*)&lo[row][fc * 4 + 2] = pack_bf16x2(l2, l3);
    }
}

// one k16 step: C += Ahi*Bhi + Ahi*Blo + Alo*Bhi
__device__ __forceinline__ void mma_k16(
    float (&c)[2][8][4],
    const __nv_bfloat16 (*Ahi)[SM_LD], const __nv_bfloat16 (*Alo)[SM_LD],
    const __nv_bfloat16 (*Bhi)[SM_LD], const __nv_bfloat16 (*Blo)[SM_LD],
    int m_local, int n_local, int lane, int k16)
{
    const int aRow = (lane & 7) + ((lane >> 3) & 1) * 8;
    const int aCol = k16 + (lane >> 4) * 8;
    const int bRow = (lane & 7) + ((lane >> 4) & 1) * 8;
    const int bCol = k16 + ((lane >> 3) & 1) * 8;
    uint32_t baseAhi = (uint32_t)__cvta_generic_to_shared(Ahi);
    uint32_t baseAlo = (uint32_t)__cvta_generic_to_shared(Alo);
    uint32_t baseBhi = (uint32_t)__cvta_generic_to_shared(Bhi);
    uint32_t baseBlo = (uint32_t)__cvta_generic_to_shared(Blo);

    uint32_t ah[2][4], al[2][4], bh[4][4], bl[4][4];
#pragma unroll
    for (int i = 0; i < 2; ++i)
        lds_x4(baseAhi + ((m_local + 16 * i + aRow) * SM_LD + aCol) * 2,
               ah[i][0], ah[i][1], ah[i][2], ah[i][3]);
#pragma unroll
    for (int jj = 0; jj < 4; ++jj)
        lds_x4(baseBhi + ((n_local + 16 * jj + bRow) * SM_LD + bCol) * 2,
               bh[jj][0], bh[jj][1], bh[jj][2], bh[jj][3]);
#pragma unroll
    for (int i = 0; i < 2; ++i)
#pragma unroll
        for (int j = 0; j < 8; ++j)
            mma_bf16(c[i][j], ah[i], bh[j >> 1][(j & 1) * 2], bh[j >> 1][(j & 1) * 2 + 1]);
#pragma unroll
    for (int jj = 0; jj < 4; ++jj)
        lds_x4(baseBlo + ((n_local + 16 * jj + bRow) * SM_LD + bCol) * 2,
               bl[jj][0], bl[jj][1], bl[jj][2], bl[jj][3]);
#pragma unroll
    for (int i = 0; i < 2; ++i)
#pragma unroll
        for (int j = 0; j < 8; ++j)
            mma_bf16(c[i][j], ah[i], bl[j >> 1][(j & 1) * 2], bl[j >> 1][(j & 1) * 2 + 1]);
#pragma unroll
    for (int i = 0; i < 2; ++i)
        lds_x4(baseAlo + ((m_local + 16 * i + aRow) * SM_LD + aCol) * 2,
               al[i][0], al[i][1], al[i][2], al[i][3]);
#pragma unroll
    for (int i = 0; i < 2; ++i)
#pragma unroll
        for (int j = 0; j < 8; ++j)
            mma_bf16(c[i][j], al[i], bh[j >> 1][(j & 1) * 2], bh[j >> 1][(j & 1) * 2 + 1]);
}

// Layer 1: h = relu( agg1 @ W1l^T + x @ W1r^T + b1 )   [M=50000, N=256, K=128]
__global__ void __launch_bounds__(256)
gemm1_mma_kernel(const float* __restrict__ x,
                 const float* __restrict__ W1l, const float* __restrict__ W1r,
                 const float* __restrict__ b1) {
    __shared__ __nv_bfloat16 Ahi[128][SM_LD], Alo[128][SM_LD];
    __shared__ __nv_bfloat16 Bhi[128][SM_LD], Blo[128][SM_LD];

    const int tid = threadIdx.x;
    const int lane = tid & 31;
    const int wid = tid >> 5;
    const int m_local = (wid & 3) * 32;
    const int n_local = (wid >> 2) * 64;
    const int m0 = blockIdx.x * 128;
    const int n0 = blockIdx.y * 128;

    float c[2][8][4];
#pragma unroll
    for (int i = 0; i < 2; ++i)
#pragma unroll
        for (int j = 0; j < 8; ++j)
#pragma unroll
            for (int k = 0; k < 4; ++k) c[i][j][k] = 0.f;

    for (int pass = 0; pass < 2; ++pass) {
        const float* A = pass ? x : g_agg1;
        const float* W = pass ? W1r : W1l;
        for (int kc = 0; kc < DIN; kc += 32) {
            __syncthreads();
            load_split_tile(A, m0, N_NODES, DIN, kc, Ahi, Alo, tid);
            load_split_tile(W, n0, 1 << 30, DIN, kc, Bhi, Blo, tid);
            __syncthreads();
            mma_k16(c, Ahi, Alo, Bhi, Blo, m_local, n_local, lane, 0);
            mma_k16(c, Ahi, Alo, Bhi, Blo, m_local, n_local, lane, 16);
        }
    }
    // epilogue: +bias, relu -> g_h
    const int gid = lane >> 2, tig = lane & 3;
#pragma unroll
    for (int i = 0; i < 2; ++i) {
        int row = m0 + m_local + 16 * i + gid;
#pragma unroll
        for (int j = 0; j < 8; ++j) {
            int col = n0 + n_local + 8 * j + 2 * tig;
            float bb0 = b1[col], bb1 = b1[col + 1];
            if (row < N_NODES) {
                float2 o = make_float2(fmaxf(c[i][j][0] + bb0, 0.f),
                                       fmaxf(c[i][j][1] + bb1, 0.f));
                *(float2*)&g_h[(size_t)row * DH + col] = o;
            }
            if (row + 8 < N_NODES) {
                float2 o = make_float2(fmaxf(c[i][j][2] + bb0, 0.f),
                                       fmaxf(c[i][j][3] + bb1, 0.f));
                *(float2*)&g_h[(size_t)(row + 8) * DH + col] = o;
            }
        }
    }
}

// Layer 2 projections: P[:,0:64] = h @ W2l^T ; P[:,64:128] = h @ W2r^T  [K=256]
__global__ void __launch_bounds__(256)
gemm2_mma_kernel(const float* __restrict__ W2l, const float* __restrict__ W2r) {
    __shared__ __nv_bfloat16 Ahi[128][SM_LD], Alo[128][SM_LD];
    __shared__ __nv_bfloat16 Bhi[128][SM_LD], Blo[128][SM_LD];

    const int tid = threadIdx.x;
    const int lane = tid & 31;
    const int wid = tid >> 5;
    const int m_local = (wid & 3) * 32;
    const int n_local = (wid >> 2) * 64;
    const int m0 = blockIdx.x * 128;

    float c[2][8][4];
#pragma unroll
    for (int i = 0; i < 2; ++i)
#pragma unroll
        for (int j = 0; j < 8; ++j)
#pragma unroll
            for (int k = 0; k < 4; ++k) c[i][j][k] = 0.f;

    for (int kc = 0; kc < DH; kc += 32) {
        __syncthreads();
        load_split_tile(g_h, m0, N_NODES, DH, kc, Ahi, Alo, tid);
        load_split_tile_w2(W2l, W2r, kc, Bhi, Blo, tid);
        __syncthreads();
        mma_k16(c, Ahi, Alo, Bhi, Blo, m_local, n_local, lane, 0);
        mma_k16(c, Ahi, Alo, Bhi, Blo, m_local, n_local, lane, 16);
    }
    const int gid = lane >> 2, tig = lane & 3;
#pragma unroll
    for (int i = 0; i < 2; ++i) {
        int row = m0 + m_local + 16 * i + gid;
#pragma unroll
        for (int j = 0; j < 8; ++j) {
            int col = n_local + 8 * j + 2 * tig;
            if (row < N_NODES)
                *(float2*)&g_P[(size_t)row * 2 * DOUT + col] =
                    make_float2(c[i][j][0], c[i][j][1]);
            if (row + 8 < N_NODES)
                *(float2*)&g_P[(size_t)(row + 8) * 2 * DOUT + col] =
                    make_float2(c[i][j][2], c[i][j][3]);
        }
    }
}

// ---- layer-2 aggregation + combine (gather, warp per node) --------------------
__global__ void __launch_bounds__(256)
agg2_final_kernel(const float* __restrict__ b2, float* __restrict__ out) {
    int w    = (blockIdx.x * blockDim.x + threadIdx.x) >> 5;
    int lane = threadIdx.x & 31;
    if (w >= N_NODES) return;
    int start = g_rowptr[w], end = g_rowptr[w + 1];
    const float2* Pv = (const float2*)g_P;
    float2 acc = make_float2(0.f, 0.f);
    int p = start;
    for (; p + 4 <= end; p += 4) {
        int s0 = g_col[p], s1 = g_col[p + 1], s2 = g_col[p + 2], s3 = g_col[p + 3];
        float2 v0 = Pv[(long long)s0 * 64 + lane];
        float2 v1 = Pv[(long long)s1 * 64 + lane];
        float2 v2 = Pv[(long long)s2 * 64 + lane];
        float2 v3 = Pv[(long long)s3 * 64 + lane];
        acc.x += v0.x + v1.x + v2.x + v3.x;
        acc.y += v0.y + v1.y + v2.y + v3.y;
    }
    for (; p < end; ++p) {
        float2 v = Pv[(long long)g_col[p] * 64 + lane];
        acc.x += v.x; acc.y += v.y;
    }
    float inv = g_inv[w];
    float2 root = Pv[(long long)w * 64 + 32 + lane];
    float2 bias = ((const float2*)b2)[lane];
    float2 o;
    o.x = acc.x * inv + root.x + bias.x;
    o.y = acc.y * inv + root.y + bias.y;
    ((float2*)out)[(long long)w * 32 + lane] = o;
}

// ---------------- launch --------------------------------------------------------
extern "C" void kernel_launch(void* const* d_in, const int* in_sizes, int n_in,
                              void* d_out, int out_size) {
    const float* x   = (const float*)d_in[0];
    const void*  ei  = d_in[1];
    const float* W1l = (const float*)d_in[2];
    const float* W1r = (const float*)d_in[3];
    const float* b1  = (const float*)d_in[4];
    const float* W2l = (const float*)d_in[5];
    const float* W2r = (const float*)d_in[6];
    const float* b2  = (const float*)d_in[7];
    float*       out = (float*)d_out;

    detect_kernel<<<1, 32>>>((const unsigned int*)ei);
    zero_cnt_kernel<<<(N_NODES + 255) / 256, 256>>>();
    count_kernel<<<(N_EDGES + 255) / 256, 256>>>(ei);
    blocksum_kernel<<<NB_SCAN, 256>>>();
    bscan_kernel<<<1, 64>>>();
    rowptr_kernel<<<NB_SCAN, 256>>>();
    cursor_init_kernel<<<(N_NODES + 255) / 256, 256>>>();
    fill_kernel<<<(N_EDGES + 255) / 256, 256>>>(ei);

    agg1_kernel<<<(N_NODES * 32 + 255) / 256, 256>>>(x);
    {
        dim3 grid((N_NODES + 127) / 128, 2);
        gemm1_mma_kernel<<<grid, 256>>>(x, W1l, W1r, b1);
    }
    {
        dim3 grid((N_NODES + 127) / 128, 1);
        gemm2_mma_kernel<<<grid, 256>>>(W2l, W2r);
    }
    agg2_final_kernel<<<(N_NODES * 32 + 255) / 256, 256>>>(b2, out);
}